// round 1
// baseline (speedup 1.0000x reference)
#include <cuda_runtime.h>
#include <math.h>

// Problem constants
#define B_   64
#define A_   128
#define M_   8
#define D_   384
#define O0_  256
#define O2_  192
#define O4_  160
#define ROWP 68          // padded SMEM row length (floats): 16B-aligned rows, no 32-bank stride

// Deterministic scratch for per-(b,a,m) partial energies (no atomics).
__device__ float g_partial[B_ * A_ * M_];

__device__ __forceinline__ float2 fma2(float2 a, float2 b, float2 c) {
    float2 d;
    asm("fma.rn.f32x2 %0, %1, %2, %3;"
        : "=l"(reinterpret_cast<unsigned long long&>(d))
        : "l"(reinterpret_cast<unsigned long long&>(a)),
          "l"(reinterpret_cast<unsigned long long&>(b)),
          "l"(reinterpret_cast<unsigned long long&>(c)));
    return d;
}

__device__ __forceinline__ float celu01(float x) {
    // F.celu(x, 0.1) = x>0 ? x : 0.1*expm1(x/0.1)
    return x > 0.f ? x : 0.1f * expm1f(10.f * x);
}

// One dense layer for all 64 batch rows: out[64,O] = celu(in[64,K] @ W^T[K,O] + bias)
// in_s / out_s are SMEM, transposed layout [k][b] with row stride ROWP.
// W global row-major [O][K]. 256 threads. warp w owns b = 8w..8w+7 (4 float2 pairs);
// lane owns o = lane + 32*j, j < O/32.
template<int K, int O>
__device__ __forceinline__ void run_layer(
    const float* __restrict__ Wg, const float* __restrict__ bg,
    const float* __restrict__ in_s, float* __restrict__ out_s,
    float* __restrict__ wt, bool docelu)
{
    constexpr int TO = O / 32;
    constexpr int KT = 16;
    constexpr int NT = K / KT;
    const int tid  = threadIdx.x;
    const int warp = tid >> 5;
    const int lane = tid & 31;

    float2 c[4][TO];
#pragma unroll
    for (int j = 0; j < TO; j++) {
        float bv = __ldg(bg + lane + 32 * j);
#pragma unroll
        for (int bp = 0; bp < 4; bp++) c[bp][j] = make_float2(bv, bv);
    }

    const bool loader = (tid < O);
    float4 rv[KT / 4];
    if (loader) {
        const float4* p = reinterpret_cast<const float4*>(Wg + (size_t)tid * K);
#pragma unroll
        for (int q = 0; q < KT / 4; q++) rv[q] = p[q];
    }

    for (int t = 0; t < NT; t++) {
        float* wb = wt + (t & 1) * (KT * 256);
        if (loader) {
#pragma unroll
            for (int q = 0; q < KT / 4; q++) {
                wb[(4 * q + 0) * O + tid] = rv[q].x;
                wb[(4 * q + 1) * O + tid] = rv[q].y;
                wb[(4 * q + 2) * O + tid] = rv[q].z;
                wb[(4 * q + 3) * O + tid] = rv[q].w;
            }
        }
        __syncthreads();
        if (t + 1 < NT && loader) {
            const float4* p = reinterpret_cast<const float4*>(
                Wg + (size_t)tid * K + (t + 1) * KT);
#pragma unroll
            for (int q = 0; q < KT / 4; q++) rv[q] = p[q];
        }
        const float* xrow = in_s + (t * KT) * ROWP + warp * 8;
#pragma unroll
        for (int ki = 0; ki < KT; ki++) {
            float4 xa = *reinterpret_cast<const float4*>(xrow + ki * ROWP);
            float4 xb = *reinterpret_cast<const float4*>(xrow + ki * ROWP + 4);
            float2 x[4] = { {xa.x, xa.y}, {xa.z, xa.w}, {xb.x, xb.y}, {xb.z, xb.w} };
#pragma unroll
            for (int j = 0; j < TO; j++) {
                float w = wb[ki * O + lane + 32 * j];
                float2 w2 = make_float2(w, w);
#pragma unroll
                for (int bp = 0; bp < 4; bp++) c[bp][j] = fma2(x[bp], w2, c[bp][j]);
            }
        }
        __syncthreads();
    }

    // Epilogue: activation + transposed store out_s[o][b]
#pragma unroll
    for (int j = 0; j < TO; j++) {
        int o = lane + 32 * j;
#pragma unroll
        for (int bp = 0; bp < 4; bp++) {
            float2 v = c[bp][j];
            if (docelu) { v.x = celu01(v.x); v.y = celu01(v.y); }
            *reinterpret_cast<float2*>(out_s + o * ROWP + warp * 8 + bp * 2) = v;
        }
    }
}

__global__ void __launch_bounds__(256, 1)
nn_kernel(const float* __restrict__ aev,
          const float* __restrict__ w0, const float* __restrict__ b0,
          const float* __restrict__ w2, const float* __restrict__ b2,
          const float* __restrict__ w4, const float* __restrict__ b4,
          const float* __restrict__ w6, const float* __restrict__ b6)
{
    extern __shared__ float smem[];
    float* regA = smem;                    // 384*68 floats
    float* regB = regA + D_ * ROWP;        // 256*68 floats
    float* wt   = regB + O0_ * ROWP;       // 2*16*256 floats

    const int am  = blockIdx.x;
    const int a   = am >> 3;
    const int tid = threadIdx.x;

    // Transpose aev[:, a, :] -> regA[k][b]
    for (int idx = tid; idx < B_ * (D_ / 4); idx += 256) {
        int b = idx / (D_ / 4);
        int q = idx % (D_ / 4);
        float4 v = *reinterpret_cast<const float4*>(
            aev + ((size_t)b * A_ + a) * D_ + q * 4);
        regA[(q * 4 + 0) * ROWP + b] = v.x;
        regA[(q * 4 + 1) * ROWP + b] = v.y;
        regA[(q * 4 + 2) * ROWP + b] = v.z;
        regA[(q * 4 + 3) * ROWP + b] = v.w;
    }
    __syncthreads();

    run_layer<D_,  O0_>(w0 + (size_t)am * O0_ * D_,  b0 + am * O0_, regA, regB, wt, true);
    __syncthreads();
    run_layer<O0_, O2_>(w2 + (size_t)am * O2_ * O0_, b2 + am * O2_, regB, regA, wt, true);
    __syncthreads();
    run_layer<O2_, O4_>(w4 + (size_t)am * O4_ * O2_, b4 + am * O4_, regA, regB, wt, true);
    __syncthreads();

    // Final layer: O=1, K=160 dot product per b. Input in regB[k][b].
    const float* w6p = w6 + am * O4_;
    const int b    = tid >> 2;
    const int part = tid & 3;
    float acc = 0.f;
#pragma unroll 8
    for (int i = 0; i < 40; i++) {
        int k = part * 40 + i;
        acc += w6p[k] * regB[k * ROWP + b];
    }
    acc += __shfl_xor_sync(0xffffffffu, acc, 1);
    acc += __shfl_xor_sync(0xffffffffu, acc, 2);
    if (part == 0) {
        g_partial[(size_t)b * (A_ * M_) + am] = acc + b6[am];
    }
}

__global__ void reduce_kernel(float* __restrict__ out, int species_first) {
    __shared__ float sh[256];
    const int b = blockIdx.x;
    float s = 0.f;
    for (int i = threadIdx.x; i < A_ * M_; i += 256)
        s += g_partial[(size_t)b * (A_ * M_) + i];
    sh[threadIdx.x] = s;
    __syncthreads();
    for (int st = 128; st > 0; st >>= 1) {
        if (threadIdx.x < st) sh[threadIdx.x] += sh[threadIdx.x + st];
        __syncthreads();
    }
    if (threadIdx.x == 0)
        out[(species_first ? B_ * A_ : 0) + b] = sh[0] / (float)M_;
}

__global__ void species_kernel(const int* __restrict__ sp, float* __restrict__ out) {
    int i = blockIdx.x * 256 + threadIdx.x;
    if (i < B_ * A_) out[i] = (float)sp[i];
}

extern "C" void kernel_launch(void* const* d_in, const int* in_sizes, int n_in,
                              void* d_out, int out_size) {
    const int*   species = (const int*)  d_in[0];
    const float* aev     = (const float*)d_in[1];
    const float* w0      = (const float*)d_in[2];
    const float* b0      = (const float*)d_in[3];
    const float* w2      = (const float*)d_in[4];
    const float* b2      = (const float*)d_in[5];
    const float* w4      = (const float*)d_in[6];
    const float* b4      = (const float*)d_in[7];
    const float* w6      = (const float*)d_in[8];
    const float* b6      = (const float*)d_in[9];
    float* out = (float*)d_out;

    const int smem_bytes = (D_ * ROWP + O0_ * ROWP + 2 * 16 * 256) * (int)sizeof(float);
    cudaFuncSetAttribute(nn_kernel, cudaFuncAttributeMaxDynamicSharedMemorySize, smem_bytes);

    nn_kernel<<<A_ * M_, 256, smem_bytes>>>(aev, w0, b0, w2, b2, w4, b4, w6, b6);

    const int species_first = (out_size >= B_ * A_ + B_) ? 1 : 0;
    if (species_first)
        species_kernel<<<(B_ * A_) / 256, 256>>>(species, out);
    reduce_kernel<<<B_, 256>>>(out, species_first);
}

// round 3
// speedup vs baseline: 1.2220x; 1.2220x over previous
#include <cuda_runtime.h>
#include <cuda_bf16.h>
#include <stdint.h>
#include <math.h>

#define B_   64
#define A_   128
#define M_   8
#define D_   384
#define O0_  256
#define O2_  192
#define O4_  160

// smem pitches (bytes) for X buffers [b][k] bf16: K*2+16 -> conflict-free frag reads
#define P0 784     // K=384
#define P1 528     // K=256
#define P2 400     // K=192

#define X0H_OFF 0
#define X0L_OFF 50176
#define X1H_OFF 100352
#define X1L_OFF 134144
#define SMEM_BYTES 167936
#define PF 68      // final f32 Y pitch (floats), layout [o][b]

__device__ float g_partial[B_ * A_ * M_];

__device__ __forceinline__ float celu01(float x) {
    return x > 0.f ? x : 0.1f * expm1f(10.f * x);
}

__device__ __forceinline__ uint32_t pack_bf16(float a, float b) {
    __nv_bfloat16 ha = __float2bfloat16(a);
    __nv_bfloat16 hb = __float2bfloat16(b);
    return ((uint32_t)__bfloat16_as_ushort(hb) << 16) | (uint32_t)__bfloat16_as_ushort(ha);
}
__device__ __forceinline__ uint32_t pack_bf16_lo(float a, float b) {
    __nv_bfloat16 ha = __float2bfloat16(a);
    __nv_bfloat16 hb = __float2bfloat16(b);
    __nv_bfloat16 ja = __float2bfloat16(a - __bfloat162float(ha));
    __nv_bfloat16 jb = __float2bfloat16(b - __bfloat162float(hb));
    return ((uint32_t)__bfloat16_as_ushort(jb) << 16) | (uint32_t)__bfloat16_as_ushort(ja);
}

__device__ __forceinline__ void mma16816(float c[4], const uint32_t a[4], const uint32_t b[2]) {
    asm volatile(
        "mma.sync.aligned.m16n8k16.row.col.f32.bf16.bf16.f32 "
        "{%0,%1,%2,%3}, {%4,%5,%6,%7}, {%8,%9}, {%0,%1,%2,%3};"
        : "+f"(c[0]), "+f"(c[1]), "+f"(c[2]), "+f"(c[3])
        : "r"(a[0]), "r"(a[1]), "r"(a[2]), "r"(a[3]), "r"(b[0]), "r"(b[1]));
}

// One layer: D[o][b] = celu(W[o][k] X[k][b] + bias). A frags direct from gmem fp32,
// B frags from smem bf16 hi/lo. 3-way split MMA.
template<int K, int O, int PIN, int POUT, bool FINAL>
__device__ __forceinline__ void layer(
    const float* __restrict__ Wg, const float* __restrict__ bias,
    const char* __restrict__ Xh, const char* __restrict__ Xl,
    char* __restrict__ Yh, char* __restrict__ Yl, float* __restrict__ Yf)
{
    const int lane  = threadIdx.x & 31;
    const int warp  = threadIdx.x >> 5;
    const int group = lane >> 2;
    const int tig   = lane & 3;
    constexpr int NMT = O / 16;
    constexpr int NK  = K / 16;
    const int nmt = (warp + 8 < NMT) ? 2 : 1;

    float acc[2][8][4];
#pragma unroll
    for (int im = 0; im < 2; im++)
#pragma unroll
        for (int nt = 0; nt < 8; nt++)
#pragma unroll
            for (int e = 0; e < 4; e++) acc[im][nt][e] = 0.f;

    float2 raw[2][4], rawn[2][4];

    // prologue A loads (kc=0)
#pragma unroll
    for (int im = 0; im < 2; im++) {
        if (im < nmt) {
            const float* p = Wg + (warp + im * 8) * 16 * K + group * K + tig * 2;
            raw[im][0] = *(const float2*)(p);
            raw[im][1] = *(const float2*)(p + 8 * K);
            raw[im][2] = *(const float2*)(p + 8);
            raw[im][3] = *(const float2*)(p + 8 * K + 8);
        }
    }

    for (int kc = 0; kc < NK; kc++) {
        // B fragments (hi & lo)
        uint32_t bh[8][2], bl[8][2];
        const int koff = (kc * 16 + tig * 2) * 2;
#pragma unroll
        for (int nt = 0; nt < 8; nt++) {
            int n = nt * 8 + group;
            const char* ph = Xh + n * PIN + koff;
            const char* pl = Xl + n * PIN + koff;
            bh[nt][0] = *(const uint32_t*)(ph);
            bh[nt][1] = *(const uint32_t*)(ph + 16);
            bl[nt][0] = *(const uint32_t*)(pl);
            bl[nt][1] = *(const uint32_t*)(pl + 16);
        }

        // prefetch next A chunk
        if (kc + 1 < NK) {
#pragma unroll
            for (int im = 0; im < 2; im++) {
                if (im < nmt) {
                    const float* p = Wg + (warp + im * 8) * 16 * K + group * K
                                     + (kc + 1) * 16 + tig * 2;
                    rawn[im][0] = *(const float2*)(p);
                    rawn[im][1] = *(const float2*)(p + 8 * K);
                    rawn[im][2] = *(const float2*)(p + 8);
                    rawn[im][3] = *(const float2*)(p + 8 * K + 8);
                }
            }
        }

#pragma unroll
        for (int im = 0; im < 2; im++) {
            if (im < nmt) {
                uint32_t ah[4], al[4];
#pragma unroll
                for (int j = 0; j < 4; j++) {
                    ah[j] = pack_bf16(raw[im][j].x, raw[im][j].y);
                    al[j] = pack_bf16_lo(raw[im][j].x, raw[im][j].y);
                }
#pragma unroll
                for (int nt = 0; nt < 8; nt++) {
                    mma16816(acc[im][nt], ah, bh[nt]);
                    mma16816(acc[im][nt], ah, bl[nt]);
                    mma16816(acc[im][nt], al, bh[nt]);
                }
            }
        }
#pragma unroll
        for (int im = 0; im < 2; im++)
#pragma unroll
            for (int j = 0; j < 4; j++) raw[im][j] = rawn[im][j];
    }

    // epilogue
#pragma unroll
    for (int im = 0; im < 2; im++) {
        if (im < nmt) {
            const int mt = warp + im * 8;
            const int o0 = mt * 16 + group;
            const int o1 = o0 + 8;
            const float bv0 = __ldg(bias + o0);
            const float bv1 = __ldg(bias + o1);
#pragma unroll
            for (int nt = 0; nt < 8; nt++) {
                const int bc = nt * 8 + tig * 2;
                float v00 = celu01(acc[im][nt][0] + bv0);
                float v01 = celu01(acc[im][nt][1] + bv0);
                float v10 = celu01(acc[im][nt][2] + bv1);
                float v11 = celu01(acc[im][nt][3] + bv1);
                if (!FINAL) {
                    __nv_bfloat16 h00 = __float2bfloat16(v00);
                    __nv_bfloat16 h01 = __float2bfloat16(v01);
                    __nv_bfloat16 h10 = __float2bfloat16(v10);
                    __nv_bfloat16 h11 = __float2bfloat16(v11);
                    *(__nv_bfloat16*)(Yh + (size_t)bc * POUT + o0 * 2)       = h00;
                    *(__nv_bfloat16*)(Yh + (size_t)(bc + 1) * POUT + o0 * 2) = h01;
                    *(__nv_bfloat16*)(Yh + (size_t)bc * POUT + o1 * 2)       = h10;
                    *(__nv_bfloat16*)(Yh + (size_t)(bc + 1) * POUT + o1 * 2) = h11;
                    *(__nv_bfloat16*)(Yl + (size_t)bc * POUT + o0 * 2)       = __float2bfloat16(v00 - __bfloat162float(h00));
                    *(__nv_bfloat16*)(Yl + (size_t)(bc + 1) * POUT + o0 * 2) = __float2bfloat16(v01 - __bfloat162float(h01));
                    *(__nv_bfloat16*)(Yl + (size_t)bc * POUT + o1 * 2)       = __float2bfloat16(v10 - __bfloat162float(h10));
                    *(__nv_bfloat16*)(Yl + (size_t)(bc + 1) * POUT + o1 * 2) = __float2bfloat16(v11 - __bfloat162float(h11));
                } else {
                    Yf[o0 * PF + bc]     = v00;
                    Yf[o0 * PF + bc + 1] = v01;
                    Yf[o1 * PF + bc]     = v10;
                    Yf[o1 * PF + bc + 1] = v11;
                }
            }
        }
    }
}

__global__ void __launch_bounds__(256, 1)
nn_hmma(const float* __restrict__ aev,
        const float* __restrict__ w0, const float* __restrict__ b0,
        const float* __restrict__ w2, const float* __restrict__ b2,
        const float* __restrict__ w4, const float* __restrict__ b4,
        const float* __restrict__ w6, const float* __restrict__ b6)
{
    extern __shared__ char sm[];
    const int tid = threadIdx.x;
    const int am = blockIdx.x, a = am >> 3;

    // init X0 from aev: [b][k] bf16 hi/lo
#pragma unroll
    for (int it = 0; it < 48; it++) {
        int f = (it * 256 + tid) * 2;
        int b = f / D_;
        int k = f % D_;
        float2 v = *(const float2*)(aev + ((size_t)b * A_ + a) * D_ + k);
        *(uint32_t*)(sm + X0H_OFF + (size_t)b * P0 + k * 2) = pack_bf16(v.x, v.y);
        *(uint32_t*)(sm + X0L_OFF + (size_t)b * P0 + k * 2) = pack_bf16_lo(v.x, v.y);
    }
    __syncthreads();

    layer<D_, O0_, P0, P1, false>(
        w0 + (size_t)am * O0_ * D_, b0 + (size_t)am * O0_,
        sm + X0H_OFF, sm + X0L_OFF, sm + X1H_OFF, sm + X1L_OFF, nullptr);
    __syncthreads();

    layer<O0_, O2_, P1, P2, false>(
        w2 + (size_t)am * O2_ * O0_, b2 + (size_t)am * O2_,
        sm + X1H_OFF, sm + X1L_OFF, sm + X0H_OFF, sm + X0L_OFF, nullptr);
    __syncthreads();

    layer<O2_, O4_, P2, 0, true>(
        w4 + (size_t)am * O4_ * O2_, b4 + (size_t)am * O4_,
        sm + X0H_OFF, sm + X0L_OFF, nullptr, nullptr, (float*)(sm + X1H_OFF));
    __syncthreads();

    // final dot: energy contribution per (b, am)
    const float* Yf = (const float*)(sm + X1H_OFF);
    const float* w6p = w6 + (size_t)am * O4_;
    const int b = tid >> 2;
    const int part = tid & 3;
    float acc = 0.f;
#pragma unroll 8
    for (int i = 0; i < 40; i++) {
        int k = part * 40 + i;
        acc += __ldg(w6p + k) * Yf[k * PF + b];
    }
    acc += __shfl_xor_sync(0xffffffffu, acc, 1);
    acc += __shfl_xor_sync(0xffffffffu, acc, 2);
    if (part == 0)
        g_partial[(size_t)b * (A_ * M_) + am] = acc + __ldg(b6 + am);
}

// ---------------- output assembly ----------------
__global__ void reduce_kernel(float* __restrict__ out, int species_first) {
    __shared__ float sh[256];
    const int b = blockIdx.x;
    float s = 0.f;
    for (int i = threadIdx.x; i < A_ * M_; i += 256)
        s += g_partial[(size_t)b * (A_ * M_) + i];
    sh[threadIdx.x] = s;
    __syncthreads();
    for (int st = 128; st > 0; st >>= 1) {
        if (threadIdx.x < st) sh[threadIdx.x] += sh[threadIdx.x + st];
        __syncthreads();
    }
    if (threadIdx.x == 0)
        out[(species_first ? B_ * A_ : 0) + b] = sh[0] / (float)M_;
}

__global__ void species_kernel(const int* __restrict__ sp, float* __restrict__ out) {
    int i = blockIdx.x * 256 + threadIdx.x;
    if (i < B_ * A_) out[i] = (float)sp[i];
}

extern "C" void kernel_launch(void* const* d_in, const int* in_sizes, int n_in,
                              void* d_out, int out_size) {
    const int*   species = (const int*)  d_in[0];
    const float* aev     = (const float*)d_in[1];
    const float* w0      = (const float*)d_in[2];
    const float* b0      = (const float*)d_in[3];
    const float* w2      = (const float*)d_in[4];
    const float* b2      = (const float*)d_in[5];
    const float* w4      = (const float*)d_in[6];
    const float* b4      = (const float*)d_in[7];
    const float* w6      = (const float*)d_in[8];
    const float* b6      = (const float*)d_in[9];
    float* out = (float*)d_out;

    cudaFuncSetAttribute(nn_hmma, cudaFuncAttributeMaxDynamicSharedMemorySize, SMEM_BYTES);

    nn_hmma<<<A_ * M_, 256, SMEM_BYTES>>>(aev, w0, b0, w2, b2, w4, b4, w6, b6);

    const int species_first = (out_size >= B_ * A_ + B_) ? 1 : 0;
    if (species_first)
        species_kernel<<<(B_ * A_) / 256, 256>>>(species, out);
    reduce_kernel<<<B_, 256>>>(out, species_first);
}

// round 4
// speedup vs baseline: 2.1344x; 1.7467x over previous
#include <cuda_runtime.h>
#include <cuda_bf16.h>
#include <stdint.h>
#include <math.h>

#define B_   64
#define A_   128
#define M_   8
#define D_   384
#define O0_  256
#define O2_  192
#define O4_  160

// smem pitches (bytes) for X buffers [b][k] bf16: K*2+16 -> conflict-free frag reads
#define P0 784     // K=384
#define P1 528     // K=256
#define P2 400     // K=192

#define X0H_OFF 0
#define X0L_OFF 50176
#define X1H_OFF 100352
#define X1L_OFF 134144
#define SMEM_BYTES 167936
#define PF 68      // final f32 Y pitch (floats), layout [o][b]

#define NTHREADS 512

__device__ float g_partial[B_ * A_ * M_];

__device__ __forceinline__ float celu01(float x) {
    return x > 0.f ? x : 0.1f * expm1f(10.f * x);
}

__device__ __forceinline__ uint32_t pack_bf16(float a, float b) {
    __nv_bfloat16 ha = __float2bfloat16(a);
    __nv_bfloat16 hb = __float2bfloat16(b);
    return ((uint32_t)__bfloat16_as_ushort(hb) << 16) | (uint32_t)__bfloat16_as_ushort(ha);
}
__device__ __forceinline__ uint32_t pack_bf16_lo(float a, float b) {
    __nv_bfloat16 ha = __float2bfloat16(a);
    __nv_bfloat16 hb = __float2bfloat16(b);
    __nv_bfloat16 ja = __float2bfloat16(a - __bfloat162float(ha));
    __nv_bfloat16 jb = __float2bfloat16(b - __bfloat162float(hb));
    return ((uint32_t)__bfloat16_as_ushort(jb) << 16) | (uint32_t)__bfloat16_as_ushort(ja);
}

__device__ __forceinline__ void mma16816(float c[4], const uint32_t a[4], const uint32_t b[2]) {
    asm volatile(
        "mma.sync.aligned.m16n8k16.row.col.f32.bf16.bf16.f32 "
        "{%0,%1,%2,%3}, {%4,%5,%6,%7}, {%8,%9}, {%0,%1,%2,%3};"
        : "+f"(c[0]), "+f"(c[1]), "+f"(c[2]), "+f"(c[3])
        : "r"(a[0]), "r"(a[1]), "r"(a[2]), "r"(a[3]), "r"(b[0]), "r"(b[1]));
}

// One layer: D[o][b] = celu(W[o][k] X[k][b] + bias).
// 16 warps: warp = (g<<3)|wm. Group g handles n-tiles [g*4, g*4+4);
// warp wm handles m-tiles {wm, wm+8} (where < O/16). A frags streamed from gmem
// (group g=1 duplicates g=0's loads -> L1 hits). 3-way bf16 split MMA.
template<int K, int O, int PIN, int POUT, bool FINAL>
__device__ __forceinline__ void layer(
    const float* __restrict__ Wg, const float* __restrict__ bias,
    const char* __restrict__ Xh, const char* __restrict__ Xl,
    char* __restrict__ Yh, char* __restrict__ Yl, float* __restrict__ Yf)
{
    const int lane  = threadIdx.x & 31;
    const int warp  = threadIdx.x >> 5;
    const int wm    = warp & 7;
    const int g     = warp >> 3;
    const int group = lane >> 2;
    const int tig   = lane & 3;
    constexpr int NMT = O / 16;
    constexpr int NK  = K / 16;
    const int nmt = (wm + 8 < NMT) ? 2 : 1;

    float acc[2][4][4];
#pragma unroll
    for (int im = 0; im < 2; im++)
#pragma unroll
        for (int j = 0; j < 4; j++)
#pragma unroll
            for (int e = 0; e < 4; e++) acc[im][j][e] = 0.f;

    float2 raw[2][4], rawn[2][4];

    // prologue A loads (kc=0)
#pragma unroll
    for (int im = 0; im < 2; im++) {
        if (im < nmt) {
            const float* p = Wg + (size_t)(wm + im * 8) * 16 * K + group * K + tig * 2;
            raw[im][0] = *(const float2*)(p);
            raw[im][1] = *(const float2*)(p + 8 * K);
            raw[im][2] = *(const float2*)(p + 8);
            raw[im][3] = *(const float2*)(p + 8 * K + 8);
        }
    }

    for (int kc = 0; kc < NK; kc++) {
        // B fragments for this group's 4 n-tiles (hi & lo)
        uint32_t bh[4][2], bl[4][2];
        const int koff = (kc * 16 + tig * 2) * 2;
#pragma unroll
        for (int j = 0; j < 4; j++) {
            int n = (g * 4 + j) * 8 + group;
            const char* ph = Xh + (size_t)n * PIN + koff;
            const char* pl = Xl + (size_t)n * PIN + koff;
            bh[j][0] = *(const uint32_t*)(ph);
            bh[j][1] = *(const uint32_t*)(ph + 16);
            bl[j][0] = *(const uint32_t*)(pl);
            bl[j][1] = *(const uint32_t*)(pl + 16);
        }

        // prefetch next A chunk
        if (kc + 1 < NK) {
#pragma unroll
            for (int im = 0; im < 2; im++) {
                if (im < nmt) {
                    const float* p = Wg + (size_t)(wm + im * 8) * 16 * K + group * K
                                     + (kc + 1) * 16 + tig * 2;
                    rawn[im][0] = *(const float2*)(p);
                    rawn[im][1] = *(const float2*)(p + 8 * K);
                    rawn[im][2] = *(const float2*)(p + 8);
                    rawn[im][3] = *(const float2*)(p + 8 * K + 8);
                }
            }
        }

#pragma unroll
        for (int im = 0; im < 2; im++) {
            if (im < nmt) {
                uint32_t ah[4], al[4];
#pragma unroll
                for (int j = 0; j < 4; j++) {
                    ah[j] = pack_bf16(raw[im][j].x, raw[im][j].y);
                    al[j] = pack_bf16_lo(raw[im][j].x, raw[im][j].y);
                }
#pragma unroll
                for (int j = 0; j < 4; j++) {
                    mma16816(acc[im][j], ah, bh[j]);
                    mma16816(acc[im][j], ah, bl[j]);
                    mma16816(acc[im][j], al, bh[j]);
                }
            }
        }
#pragma unroll
        for (int im = 0; im < 2; im++)
#pragma unroll
            for (int j = 0; j < 4; j++) raw[im][j] = rawn[im][j];
    }

    // epilogue
#pragma unroll
    for (int im = 0; im < 2; im++) {
        if (im < nmt) {
            const int mt = wm + im * 8;
            const int o0 = mt * 16 + group;
            const int o1 = o0 + 8;
            const float bv0 = __ldg(bias + o0);
            const float bv1 = __ldg(bias + o1);
#pragma unroll
            for (int j = 0; j < 4; j++) {
                const int bc = (g * 4 + j) * 8 + tig * 2;
                float v00 = celu01(acc[im][j][0] + bv0);
                float v01 = celu01(acc[im][j][1] + bv0);
                float v10 = celu01(acc[im][j][2] + bv1);
                float v11 = celu01(acc[im][j][3] + bv1);
                if (!FINAL) {
                    __nv_bfloat16 h00 = __float2bfloat16(v00);
                    __nv_bfloat16 h01 = __float2bfloat16(v01);
                    __nv_bfloat16 h10 = __float2bfloat16(v10);
                    __nv_bfloat16 h11 = __float2bfloat16(v11);
                    *(__nv_bfloat16*)(Yh + (size_t)bc * POUT + o0 * 2)       = h00;
                    *(__nv_bfloat16*)(Yh + (size_t)(bc + 1) * POUT + o0 * 2) = h01;
                    *(__nv_bfloat16*)(Yh + (size_t)bc * POUT + o1 * 2)       = h10;
                    *(__nv_bfloat16*)(Yh + (size_t)(bc + 1) * POUT + o1 * 2) = h11;
                    *(__nv_bfloat16*)(Yl + (size_t)bc * POUT + o0 * 2)       = __float2bfloat16(v00 - __bfloat162float(h00));
                    *(__nv_bfloat16*)(Yl + (size_t)(bc + 1) * POUT + o0 * 2) = __float2bfloat16(v01 - __bfloat162float(h01));
                    *(__nv_bfloat16*)(Yl + (size_t)bc * POUT + o1 * 2)       = __float2bfloat16(v10 - __bfloat162float(h10));
                    *(__nv_bfloat16*)(Yl + (size_t)(bc + 1) * POUT + o1 * 2) = __float2bfloat16(v11 - __bfloat162float(h11));
                } else {
                    Yf[o0 * PF + bc]     = v00;
                    Yf[o0 * PF + bc + 1] = v01;
                    Yf[o1 * PF + bc]     = v10;
                    Yf[o1 * PF + bc + 1] = v11;
                }
            }
        }
    }
}

__global__ void __launch_bounds__(NTHREADS, 1)
nn_hmma(const float* __restrict__ aev,
        const float* __restrict__ w0, const float* __restrict__ b0,
        const float* __restrict__ w2, const float* __restrict__ b2,
        const float* __restrict__ w4, const float* __restrict__ b4,
        const float* __restrict__ w6, const float* __restrict__ b6)
{
    extern __shared__ char sm[];
    const int tid = threadIdx.x;
    const int am = blockIdx.x, a = am >> 3;

    // init X0 from aev: [b][k] bf16 hi/lo
#pragma unroll
    for (int it = 0; it < 24; it++) {
        int f = (it * NTHREADS + tid) * 2;
        int b = f / D_;
        int k = f % D_;
        float2 v = *(const float2*)(aev + ((size_t)b * A_ + a) * D_ + k);
        *(uint32_t*)(sm + X0H_OFF + (size_t)b * P0 + k * 2) = pack_bf16(v.x, v.y);
        *(uint32_t*)(sm + X0L_OFF + (size_t)b * P0 + k * 2) = pack_bf16_lo(v.x, v.y);
    }
    __syncthreads();

    layer<D_, O0_, P0, P1, false>(
        w0 + (size_t)am * O0_ * D_, b0 + (size_t)am * O0_,
        sm + X0H_OFF, sm + X0L_OFF, sm + X1H_OFF, sm + X1L_OFF, nullptr);
    __syncthreads();

    layer<O0_, O2_, P1, P2, false>(
        w2 + (size_t)am * O2_ * O0_, b2 + (size_t)am * O2_,
        sm + X1H_OFF, sm + X1L_OFF, sm + X0H_OFF, sm + X0L_OFF, nullptr);
    __syncthreads();

    layer<O2_, O4_, P2, 0, true>(
        w4 + (size_t)am * O4_ * O2_, b4 + (size_t)am * O4_,
        sm + X0H_OFF, sm + X0L_OFF, nullptr, nullptr, (float*)(sm + X1H_OFF));
    __syncthreads();

    // final dot: energy contribution per (b, am). 512 threads: 8 per b.
    const float* Yf = (const float*)(sm + X1H_OFF);
    const float* w6p = w6 + (size_t)am * O4_;
    const int b = tid >> 3;
    const int part = tid & 7;
    float acc = 0.f;
#pragma unroll
    for (int i = 0; i < 20; i++) {
        int k = part * 20 + i;
        acc += __ldg(w6p + k) * Yf[k * PF + b];
    }
    acc += __shfl_xor_sync(0xffffffffu, acc, 1);
    acc += __shfl_xor_sync(0xffffffffu, acc, 2);
    acc += __shfl_xor_sync(0xffffffffu, acc, 4);
    if (part == 0)
        g_partial[(size_t)b * (A_ * M_) + am] = acc + __ldg(b6 + am);
}

// ---------------- output assembly ----------------
__global__ void reduce_kernel(float* __restrict__ out, int species_first) {
    __shared__ float sh[256];
    const int b = blockIdx.x;
    float s = 0.f;
    for (int i = threadIdx.x; i < A_ * M_; i += 256)
        s += g_partial[(size_t)b * (A_ * M_) + i];
    sh[threadIdx.x] = s;
    __syncthreads();
    for (int st = 128; st > 0; st >>= 1) {
        if (threadIdx.x < st) sh[threadIdx.x] += sh[threadIdx.x + st];
        __syncthreads();
    }
    if (threadIdx.x == 0)
        out[(species_first ? B_ * A_ : 0) + b] = sh[0] / (float)M_;
}

__global__ void species_kernel(const int* __restrict__ sp, float* __restrict__ out) {
    int i = blockIdx.x * 256 + threadIdx.x;
    if (i < B_ * A_) out[i] = (float)sp[i];
}

extern "C" void kernel_launch(void* const* d_in, const int* in_sizes, int n_in,
                              void* d_out, int out_size) {
    const int*   species = (const int*)  d_in[0];
    const float* aev     = (const float*)d_in[1];
    const float* w0      = (const float*)d_in[2];
    const float* b0      = (const float*)d_in[3];
    const float* w2      = (const float*)d_in[4];
    const float* b2      = (const float*)d_in[5];
    const float* w4      = (const float*)d_in[6];
    const float* b4      = (const float*)d_in[7];
    const float* w6      = (const float*)d_in[8];
    const float* b6      = (const float*)d_in[9];
    float* out = (float*)d_out;

    cudaFuncSetAttribute(nn_hmma, cudaFuncAttributeMaxDynamicSharedMemorySize, SMEM_BYTES);

    nn_hmma<<<A_ * M_, NTHREADS, SMEM_BYTES>>>(aev, w0, b0, w2, b2, w4, b4, w6, b6);

    const int species_first = (out_size >= B_ * A_ + B_) ? 1 : 0;
    if (species_first)
        species_kernel<<<(B_ * A_) / 256, 256>>>(species, out);
    reduce_kernel<<<B_, 256>>>(out, species_first);
}

// round 5
// speedup vs baseline: 2.2778x; 1.0672x over previous
#include <cuda_runtime.h>
#include <cuda_bf16.h>
#include <stdint.h>
#include <math.h>

#define B_   64
#define A_   128
#define M_   8
#define D_   384
#define O0_  256
#define O2_  192
#define O4_  160

// smem pitches (bytes) for X buffers [b][k] bf16: K*2+16 -> conflict-free LDSM rows
#define P0 784     // K=384
#define P1 528     // K=256
#define P2 400     // K=192

#define X0H_OFF 0
#define X0L_OFF 50176
#define X1H_OFF 100352
#define X1L_OFF 134144
#define SMEM_BYTES 167936
#define PF 68      // final f32 Y pitch (floats), layout [o][b]

#define NTHREADS 512

__device__ float g_partial[B_ * A_ * M_];

__device__ __forceinline__ float celu01(float x) {
    return x > 0.f ? x : 0.1f * expm1f(10.f * x);
}

__device__ __forceinline__ uint32_t smem_u32(const void* p) {
    uint32_t a;
    asm("{ .reg .u64 t; cvta.to.shared.u64 t, %1; cvt.u32.u64 %0, t; }" : "=r"(a) : "l"(p));
    return a;
}

// pack two floats to bf16x2: lo half = x, hi half = y (single F2FP)
__device__ __forceinline__ uint32_t cvt2(float x, float y) {
    uint32_t r;
    asm("cvt.rn.bf16x2.f32 %0, %1, %2;" : "=r"(r) : "f"(y), "f"(x));
    return r;
}
// hi pack + residual lo pack from a float2
__device__ __forceinline__ void split2(float x, float y, uint32_t& hi, uint32_t& lo) {
    hi = cvt2(x, y);
    float hx = __uint_as_float(hi << 16);
    float hy = __uint_as_float(hi & 0xFFFF0000u);
    lo = cvt2(x - hx, y - hy);
}

__device__ __forceinline__ void ldsm_x4(uint32_t& r0, uint32_t& r1, uint32_t& r2, uint32_t& r3,
                                        uint32_t addr) {
    asm volatile("ldmatrix.sync.aligned.m8n8.x4.shared.b16 {%0,%1,%2,%3}, [%4];"
                 : "=r"(r0), "=r"(r1), "=r"(r2), "=r"(r3) : "r"(addr));
}

__device__ __forceinline__ void mma16816(float c[4], const uint32_t a[4], const uint32_t b[2]) {
    asm volatile(
        "mma.sync.aligned.m16n8k16.row.col.f32.bf16.bf16.f32 "
        "{%0,%1,%2,%3}, {%4,%5,%6,%7}, {%8,%9}, {%0,%1,%2,%3};"
        : "+f"(c[0]), "+f"(c[1]), "+f"(c[2]), "+f"(c[3])
        : "r"(a[0]), "r"(a[1]), "r"(a[2]), "r"(a[3]), "r"(b[0]), "r"(b[1]));
}

// One layer: D[o][b] = celu(W[o][k] X[k][b] + bias).
// 16 warps: warp = (g<<3)|wm. Group g handles n-tiles [g*4, g*4+4);
// warp wm handles m-tiles {wm, wm+8} (where < O/16). A frags streamed from gmem.
// B frags via ldmatrix.x4 (hi+lo in one instruction per n-tile). 3-way split MMA.
template<int K, int O, int PIN, int POUT, bool FINAL>
__device__ __forceinline__ void layer(
    const float* __restrict__ Wg, const float* __restrict__ bias,
    const char* __restrict__ Xh, const char* __restrict__ Xl,
    char* __restrict__ Yh, char* __restrict__ Yl, float* __restrict__ Yf)
{
    const int lane  = threadIdx.x & 31;
    const int warp  = threadIdx.x >> 5;
    const int wm    = warp & 7;
    const int g     = warp >> 3;
    const int group = lane >> 2;
    const int tig   = lane & 3;
    constexpr int NMT = O / 16;
    constexpr int NK  = K / 16;
    const int nmt = (wm + 8 < NMT) ? 2 : 1;

    // per-lane ldmatrix addresses: quad q=lane>>3 selects {Xh k0, Xh k8, Xl k0, Xl k8}
    const int q = lane >> 3;
    const int rr = lane & 7;
    uint32_t xb = (q < 2 ? smem_u32(Xh) : smem_u32(Xl)) + (uint32_t)((q & 1) * 16);
    uint32_t aj[4];
#pragma unroll
    for (int j = 0; j < 4; j++)
        aj[j] = xb + (uint32_t)(((g * 4 + j) * 8 + rr) * PIN);

    float acc[2][4][4];
#pragma unroll
    for (int im = 0; im < 2; im++)
#pragma unroll
        for (int j = 0; j < 4; j++)
#pragma unroll
            for (int e = 0; e < 4; e++) acc[im][j][e] = 0.f;

    float2 raw[2][4], rawn[2][4];

    // prologue A loads (kc=0)
#pragma unroll
    for (int im = 0; im < 2; im++) {
        if (im < nmt) {
            const float* p = Wg + (size_t)(wm + im * 8) * 16 * K + group * K + tig * 2;
            raw[im][0] = *(const float2*)(p);
            raw[im][1] = *(const float2*)(p + 8 * K);
            raw[im][2] = *(const float2*)(p + 8);
            raw[im][3] = *(const float2*)(p + 8 * K + 8);
        }
    }

    for (int kc = 0; kc < NK; kc++) {
        // B fragments: one ldmatrix.x4 per n-tile (bh0, bh1, bl0, bl1)
        uint32_t bh[4][2], bl[4][2];
#pragma unroll
        for (int j = 0; j < 4; j++)
            ldsm_x4(bh[j][0], bh[j][1], bl[j][0], bl[j][1], aj[j] + (uint32_t)(kc * 32));

        // prefetch next A chunk
        if (kc + 1 < NK) {
#pragma unroll
            for (int im = 0; im < 2; im++) {
                if (im < nmt) {
                    const float* p = Wg + (size_t)(wm + im * 8) * 16 * K + group * K
                                     + (kc + 1) * 16 + tig * 2;
                    rawn[im][0] = *(const float2*)(p);
                    rawn[im][1] = *(const float2*)(p + 8 * K);
                    rawn[im][2] = *(const float2*)(p + 8);
                    rawn[im][3] = *(const float2*)(p + 8 * K + 8);
                }
            }
        }

#pragma unroll
        for (int im = 0; im < 2; im++) {
            if (im < nmt) {
                uint32_t ah[4], al[4];
#pragma unroll
                for (int j = 0; j < 4; j++)
                    split2(raw[im][j].x, raw[im][j].y, ah[j], al[j]);
#pragma unroll
                for (int j = 0; j < 4; j++) {
                    mma16816(acc[im][j], ah, bh[j]);
                    mma16816(acc[im][j], ah, bl[j]);
                    mma16816(acc[im][j], al, bh[j]);
                }
            }
        }
#pragma unroll
        for (int im = 0; im < 2; im++)
#pragma unroll
            for (int j = 0; j < 4; j++) raw[im][j] = rawn[im][j];
    }

    // epilogue
#pragma unroll
    for (int im = 0; im < 2; im++) {
        if (im < nmt) {
            const int mt = wm + im * 8;
            const int o0 = mt * 16 + group;
            const int o1 = o0 + 8;
            const float bv0 = __ldg(bias + o0);
            const float bv1 = __ldg(bias + o1);
#pragma unroll
            for (int j = 0; j < 4; j++) {
                const int bc = (g * 4 + j) * 8 + tig * 2;
                float v00 = celu01(acc[im][j][0] + bv0);
                float v01 = celu01(acc[im][j][1] + bv0);
                float v10 = celu01(acc[im][j][2] + bv1);
                float v11 = celu01(acc[im][j][3] + bv1);
                if (!FINAL) {
                    __nv_bfloat16 h00 = __float2bfloat16(v00);
                    __nv_bfloat16 h01 = __float2bfloat16(v01);
                    __nv_bfloat16 h10 = __float2bfloat16(v10);
                    __nv_bfloat16 h11 = __float2bfloat16(v11);
                    *(__nv_bfloat16*)(Yh + (size_t)bc * POUT + o0 * 2)       = h00;
                    *(__nv_bfloat16*)(Yh + (size_t)(bc + 1) * POUT + o0 * 2) = h01;
                    *(__nv_bfloat16*)(Yh + (size_t)bc * POUT + o1 * 2)       = h10;
                    *(__nv_bfloat16*)(Yh + (size_t)(bc + 1) * POUT + o1 * 2) = h11;
                    *(__nv_bfloat16*)(Yl + (size_t)bc * POUT + o0 * 2)       = __float2bfloat16(v00 - __bfloat162float(h00));
                    *(__nv_bfloat16*)(Yl + (size_t)(bc + 1) * POUT + o0 * 2) = __float2bfloat16(v01 - __bfloat162float(h01));
                    *(__nv_bfloat16*)(Yl + (size_t)bc * POUT + o1 * 2)       = __float2bfloat16(v10 - __bfloat162float(h10));
                    *(__nv_bfloat16*)(Yl + (size_t)(bc + 1) * POUT + o1 * 2) = __float2bfloat16(v11 - __bfloat162float(h11));
                } else {
                    Yf[o0 * PF + bc]     = v00;
                    Yf[o0 * PF + bc + 1] = v01;
                    Yf[o1 * PF + bc]     = v10;
                    Yf[o1 * PF + bc + 1] = v11;
                }
            }
        }
    }
}

__global__ void __launch_bounds__(NTHREADS, 1)
nn_hmma(const float* __restrict__ aev,
        const float* __restrict__ w0, const float* __restrict__ b0,
        const float* __restrict__ w2, const float* __restrict__ b2,
        const float* __restrict__ w4, const float* __restrict__ b4,
        const float* __restrict__ w6, const float* __restrict__ b6)
{
    extern __shared__ char sm[];
    const int tid = threadIdx.x;
    const int am = blockIdx.x, a = am >> 3;

    // init X0 from aev: [b][k] bf16 hi/lo
#pragma unroll
    for (int it = 0; it < 24; it++) {
        int f = (it * NTHREADS + tid) * 2;
        int b = f / D_;
        int k = f % D_;
        float2 v = *(const float2*)(aev + ((size_t)b * A_ + a) * D_ + k);
        uint32_t hi, lo;
        split2(v.x, v.y, hi, lo);
        *(uint32_t*)(sm + X0H_OFF + (size_t)b * P0 + k * 2) = hi;
        *(uint32_t*)(sm + X0L_OFF + (size_t)b * P0 + k * 2) = lo;
    }
    __syncthreads();

    layer<D_, O0_, P0, P1, false>(
        w0 + (size_t)am * O0_ * D_, b0 + (size_t)am * O0_,
        sm + X0H_OFF, sm + X0L_OFF, sm + X1H_OFF, sm + X1L_OFF, nullptr);
    __syncthreads();

    layer<O0_, O2_, P1, P2, false>(
        w2 + (size_t)am * O2_ * O0_, b2 + (size_t)am * O2_,
        sm + X1H_OFF, sm + X1L_OFF, sm + X0H_OFF, sm + X0L_OFF, nullptr);
    __syncthreads();

    layer<O2_, O4_, P2, 0, true>(
        w4 + (size_t)am * O4_ * O2_, b4 + (size_t)am * O4_,
        sm + X0H_OFF, sm + X0L_OFF, nullptr, nullptr, (float*)(sm + X1H_OFF));
    __syncthreads();

    // final dot: energy contribution per (b, am). 512 threads: 8 per b.
    const float* Yf = (const float*)(sm + X1H_OFF);
    const float* w6p = w6 + (size_t)am * O4_;
    const int b = tid >> 3;
    const int part = tid & 7;
    float acc = 0.f;
#pragma unroll
    for (int i = 0; i < 20; i++) {
        int k = part * 20 + i;
        acc += __ldg(w6p + k) * Yf[k * PF + b];
    }
    acc += __shfl_xor_sync(0xffffffffu, acc, 1);
    acc += __shfl_xor_sync(0xffffffffu, acc, 2);
    acc += __shfl_xor_sync(0xffffffffu, acc, 4);
    if (part == 0)
        g_partial[(size_t)b * (A_ * M_) + am] = acc + __ldg(b6 + am);
}

// ---------------- output assembly ----------------
__global__ void reduce_kernel(float* __restrict__ out, int species_first) {
    __shared__ float sh[256];
    const int b = blockIdx.x;
    float s = 0.f;
    for (int i = threadIdx.x; i < A_ * M_; i += 256)
        s += g_partial[(size_t)b * (A_ * M_) + i];
    sh[threadIdx.x] = s;
    __syncthreads();
    for (int st = 128; st > 0; st >>= 1) {
        if (threadIdx.x < st) sh[threadIdx.x] += sh[threadIdx.x + st];
        __syncthreads();
    }
    if (threadIdx.x == 0)
        out[(species_first ? B_ * A_ : 0) + b] = sh[0] / (float)M_;
}

__global__ void species_kernel(const int* __restrict__ sp, float* __restrict__ out) {
    int i = blockIdx.x * 256 + threadIdx.x;
    if (i < B_ * A_) out[i] = (float)sp[i];
}

extern "C" void kernel_launch(void* const* d_in, const int* in_sizes, int n_in,
                              void* d_out, int out_size) {
    const int*   species = (const int*)  d_in[0];
    const float* aev     = (const float*)d_in[1];
    const float* w0      = (const float*)d_in[2];
    const float* b0      = (const float*)d_in[3];
    const float* w2      = (const float*)d_in[4];
    const float* b2      = (const float*)d_in[5];
    const float* w4      = (const float*)d_in[6];
    const float* b4      = (const float*)d_in[7];
    const float* w6      = (const float*)d_in[8];
    const float* b6      = (const float*)d_in[9];
    float* out = (float*)d_out;

    cudaFuncSetAttribute(nn_hmma, cudaFuncAttributeMaxDynamicSharedMemorySize, SMEM_BYTES);

    nn_hmma<<<A_ * M_, NTHREADS, SMEM_BYTES>>>(aev, w0, b0, w2, b2, w4, b4, w6, b6);

    const int species_first = (out_size >= B_ * A_ + B_) ? 1 : 0;
    if (species_first)
        species_kernel<<<(B_ * A_) / 256, 256>>>(species, out);
    reduce_kernel<<<B_, 256>>>(out, species_first);
}